// round 2
// baseline (speedup 1.0000x reference)
#include <cuda_runtime.h>
#include <math.h>

#define D_MODEL 1024
#define D_VOCAB 32000
#define NB 4
#define SEQ 1024
#define BT (NB * SEQ)        // 4096 rows
#define NLAYERS 6
#define BTV ((long)BT * D_VOCAB)

// ---------------- scratch (device globals; no allocation allowed) ------------
__device__ float g_z  [BT * D_MODEL];
__device__ float g_yln[BT * D_MODEL];
__device__ float g_q  [BT * D_MODEL];
__device__ float g_k  [BT * D_MODEL];
__device__ float g_v  [BT * D_MODEL];
__device__ float g_s  [NB * SEQ * SEQ];
__device__ float g_o  [BT * D_MODEL];
__device__ float g_h  [BT * D_MODEL];
__device__ float g_nll[BT];

// ---------------- embedding gather ------------------------------------------
__global__ void embed_kernel(const int* __restrict__ x, const float* __restrict__ enc,
                             float* __restrict__ z) {
    int row = blockIdx.x;
    int tok = x[row];
    const float* src = enc + (long)tok * D_MODEL;
    float* dst = z + (long)row * D_MODEL;
    for (int i = threadIdx.x; i < D_MODEL; i += blockDim.x) dst[i] = src[i];
}

// ---------------- (buggy) LayerNorm:  (x - mu/sqrt(var)) * g + b,  ddof=1 ----
__global__ void ln_kernel(const float* __restrict__ in, const float* __restrict__ gamma,
                          const float* __restrict__ beta, float* __restrict__ out) {
    int row = blockIdx.x;
    const float* xr = in + (long)row * D_MODEL;
    __shared__ float red[256];
    int tid = threadIdx.x;

    float s = 0.f;
    for (int i = tid; i < D_MODEL; i += 256) s += xr[i];
    red[tid] = s; __syncthreads();
    #pragma unroll
    for (int o = 128; o > 0; o >>= 1) { if (tid < o) red[tid] += red[tid + o]; __syncthreads(); }
    float mu = red[0] / (float)D_MODEL;
    __syncthreads();

    float s2 = 0.f;
    for (int i = tid; i < D_MODEL; i += 256) { float d = xr[i] - mu; s2 += d * d; }
    red[tid] = s2; __syncthreads();
    #pragma unroll
    for (int o = 128; o > 0; o >>= 1) { if (tid < o) red[tid] += red[tid + o]; __syncthreads(); }
    float var = red[0] / (float)(D_MODEL - 1);
    float shift = mu * rsqrtf(var);        // the bug: x - mu/sqrt(var)

    float* orow = out + (long)row * D_MODEL;
    for (int i = tid; i < D_MODEL; i += 256)
        orow[i] = (xr[i] - shift) * gamma[i] + beta[i];
}

// ---------------- row softmax over SEQ --------------------------------------
__global__ void softmax_kernel(float* __restrict__ s) {
    int row = blockIdx.x;
    float* r = s + (long)row * SEQ;
    __shared__ float red[256];
    int tid = threadIdx.x;

    float m = -1e30f;
    for (int i = tid; i < SEQ; i += 256) m = fmaxf(m, r[i]);
    red[tid] = m; __syncthreads();
    #pragma unroll
    for (int o = 128; o > 0; o >>= 1) { if (tid < o) red[tid] = fmaxf(red[tid], red[tid + o]); __syncthreads(); }
    float mx = red[0]; __syncthreads();

    float sum = 0.f;
    for (int i = tid; i < SEQ; i += 256) { float e = expf(r[i] - mx); r[i] = e; sum += e; }
    red[tid] = sum; __syncthreads();
    #pragma unroll
    for (int o = 128; o > 0; o >>= 1) { if (tid < o) red[tid] += red[tid + o]; __syncthreads(); }
    float inv = 1.f / red[0];
    for (int i = tid; i < SEQ; i += 256) r[i] *= inv;
}

// ---------------- SGEMM NN: C = A(MxK) * B(KxN)  [+bias][relu][+=C] ----------
// flags: 1=relu, 2=accumulate into C, 4=add bias
__global__ __launch_bounds__(256) void sgemm_nn(
    const float* __restrict__ A, const float* __restrict__ B,
    const float* __restrict__ bias, float* __restrict__ C,
    int M, int N, int K, long sA, long sB, long sC, int flags) {
    A += (long)blockIdx.z * sA;
    B += (long)blockIdx.z * sB;
    C += (long)blockIdx.z * sC;

    __shared__ float As[8][128];
    __shared__ float Bs[8][128];
    const int tid = threadIdx.x;
    const int row0 = blockIdx.y * 128, col0 = blockIdx.x * 128;
    const int tr = (tid / 16) * 8, tc = (tid % 16) * 8;
    const int arow = tid >> 1, acol = (tid & 1) * 4;
    const int brow = tid >> 5, bcol = (tid & 31) * 4;

    const float* Aptr = A + (long)(row0 + arow) * K + acol;
    const float* Bptr = B + (long)brow * N + col0 + bcol;

    float acc[8][8];
    #pragma unroll
    for (int i = 0; i < 8; i++)
        #pragma unroll
        for (int j = 0; j < 8; j++) acc[i][j] = 0.f;

    for (int k0 = 0; k0 < K; k0 += 8) {
        float4 a = *(const float4*)(Aptr + k0);
        As[acol + 0][arow] = a.x; As[acol + 1][arow] = a.y;
        As[acol + 2][arow] = a.z; As[acol + 3][arow] = a.w;
        *(float4*)&Bs[brow][bcol] = *(const float4*)(Bptr + (long)k0 * N);
        __syncthreads();
        #pragma unroll
        for (int kk = 0; kk < 8; kk++) {
            float ar[8], br[8];
            *(float4*)(ar)     = *(float4*)&As[kk][tr];
            *(float4*)(ar + 4) = *(float4*)&As[kk][tr + 4];
            *(float4*)(br)     = *(float4*)&Bs[kk][tc];
            *(float4*)(br + 4) = *(float4*)&Bs[kk][tc + 4];
            #pragma unroll
            for (int i = 0; i < 8; i++)
                #pragma unroll
                for (int j = 0; j < 8; j++)
                    acc[i][j] = fmaf(ar[i], br[j], acc[i][j]);
        }
        __syncthreads();
    }

    #pragma unroll
    for (int i = 0; i < 8; i++) {
        #pragma unroll
        for (int j = 0; j < 8; j++) {
            float v = acc[i][j];
            if (flags & 4) v += bias[col0 + tc + j];
            if (flags & 1) v = fmaxf(v, 0.f);
            float* cp = &C[(long)(row0 + tr + i) * N + col0 + tc + j];
            if (flags & 2) v += *cp;
            *cp = v;
        }
    }
}

// ---------------- SGEMM NT: C = alpha * A(MxK) * B(NxK)^T --------------------
__global__ __launch_bounds__(256) void sgemm_nt(
    const float* __restrict__ A, const float* __restrict__ B,
    float* __restrict__ C, int M, int N, int K,
    long sA, long sB, long sC, float alpha) {
    A += (long)blockIdx.z * sA;
    B += (long)blockIdx.z * sB;
    C += (long)blockIdx.z * sC;

    __shared__ float As[8][128];
    __shared__ float Bs[8][128];
    const int tid = threadIdx.x;
    const int row0 = blockIdx.y * 128, col0 = blockIdx.x * 128;
    const int tr = (tid / 16) * 8, tc = (tid % 16) * 8;
    const int arow = tid >> 1, acol = (tid & 1) * 4;

    const float* Aptr = A + (long)(row0 + arow) * K + acol;
    const float* Bptr = B + (long)(col0 + arow) * K + acol;

    float acc[8][8];
    #pragma unroll
    for (int i = 0; i < 8; i++)
        #pragma unroll
        for (int j = 0; j < 8; j++) acc[i][j] = 0.f;

    for (int k0 = 0; k0 < K; k0 += 8) {
        float4 a = *(const float4*)(Aptr + k0);
        As[acol + 0][arow] = a.x; As[acol + 1][arow] = a.y;
        As[acol + 2][arow] = a.z; As[acol + 3][arow] = a.w;
        float4 b = *(const float4*)(Bptr + k0);
        Bs[acol + 0][arow] = b.x; Bs[acol + 1][arow] = b.y;
        Bs[acol + 2][arow] = b.z; Bs[acol + 3][arow] = b.w;
        __syncthreads();
        #pragma unroll
        for (int kk = 0; kk < 8; kk++) {
            float ar[8], br[8];
            *(float4*)(ar)     = *(float4*)&As[kk][tr];
            *(float4*)(ar + 4) = *(float4*)&As[kk][tr + 4];
            *(float4*)(br)     = *(float4*)&Bs[kk][tc];
            *(float4*)(br + 4) = *(float4*)&Bs[kk][tc + 4];
            #pragma unroll
            for (int i = 0; i < 8; i++)
                #pragma unroll
                for (int j = 0; j < 8; j++)
                    acc[i][j] = fmaf(ar[i], br[j], acc[i][j]);
        }
        __syncthreads();
    }

    #pragma unroll
    for (int i = 0; i < 8; i++)
        #pragma unroll
        for (int j = 0; j < 8; j++)
            C[(long)(row0 + tr + i) * N + col0 + tc + j] = acc[i][j] * alpha;
}

// ---------------- per-row NLL over V=32000 ----------------------------------
__global__ void nll_kernel(const float* __restrict__ logits, const int* __restrict__ y,
                           float* __restrict__ nll) {
    int row = blockIdx.x;
    const float* r = logits + (long)row * D_VOCAB;
    __shared__ float red[256];
    int tid = threadIdx.x;

    float m = -1e30f;
    for (int i = tid; i < D_VOCAB; i += 256) m = fmaxf(m, r[i]);
    red[tid] = m; __syncthreads();
    #pragma unroll
    for (int o = 128; o > 0; o >>= 1) { if (tid < o) red[tid] = fmaxf(red[tid], red[tid + o]); __syncthreads(); }
    float mx = red[0]; __syncthreads();

    float s = 0.f;
    for (int i = tid; i < D_VOCAB; i += 256) s += expf(r[i] - mx);
    red[tid] = s; __syncthreads();
    #pragma unroll
    for (int o = 128; o > 0; o >>= 1) { if (tid < o) red[tid] += red[tid + o]; __syncthreads(); }

    if (tid == 0) nll[row] = (mx + logf(red[0])) - r[y[row]];
}

__global__ void loss_reduce_kernel(const float* __restrict__ nll, float* __restrict__ out,
                                   long ofs) {
    __shared__ float red[256];
    int tid = threadIdx.x;
    float s = 0.f;
    for (int i = tid; i < BT; i += 256) s += nll[i];
    red[tid] = s; __syncthreads();
    #pragma unroll
    for (int o = 128; o > 0; o >>= 1) { if (tid < o) red[tid] += red[tid + o]; __syncthreads(); }
    if (tid == 0) out[ofs] = red[0] / (float)BT;
}

// ---------------- driver -----------------------------------------------------
extern "C" void kernel_launch(void* const* d_in, const int* in_sizes, int n_in,
                              void* d_out, int out_size) {
    (void)in_sizes; (void)n_in;
    const int*   x   = (const int*)  d_in[0];
    const int*   y   = (const int*)  d_in[1];
    const float* enc = (const float*)d_in[2];
    const float* g1  = (const float*)d_in[3];
    const float* b1  = (const float*)d_in[4];
    const float* wq  = (const float*)d_in[5];
    const float* wk  = (const float*)d_in[6];
    const float* wv  = (const float*)d_in[7];
    const float* g2  = (const float*)d_in[8];
    const float* b2  = (const float*)d_in[9];
    const float* w1  = (const float*)d_in[10];
    const float* bb1 = (const float*)d_in[11];
    const float* w2  = (const float*)d_in[12];
    const float* bb2 = (const float*)d_in[13];
    float* out = (float*)d_out;

    float *z, *yln, *q, *k, *v, *s, *o, *h, *nll;
    cudaGetSymbolAddress((void**)&z,   g_z);
    cudaGetSymbolAddress((void**)&yln, g_yln);
    cudaGetSymbolAddress((void**)&q,   g_q);
    cudaGetSymbolAddress((void**)&k,   g_k);
    cudaGetSymbolAddress((void**)&v,   g_v);
    cudaGetSymbolAddress((void**)&s,   g_s);
    cudaGetSymbolAddress((void**)&o,   g_o);
    cudaGetSymbolAddress((void**)&h,   g_h);
    cudaGetSymbolAddress((void**)&nll, g_nll);

    const long SD = (long)SEQ * D_MODEL;   // per-batch stride within (BT, D) buffers
    const long SS = (long)SEQ * SEQ;       // per-batch stride within scores

    embed_kernel<<<BT, 256>>>(x, enc, z);

    dim3 grid_proj(D_MODEL / 128, BT / 128);      // (8, 32)
    dim3 grid_attn(SEQ / 128, SEQ / 128, NB);     // (8, 8, 4)

    for (int layer = 0; layer < NLAYERS; layer++) {
        ln_kernel<<<BT, 256>>>(z, g1, b1, yln);

        sgemm_nn<<<grid_proj, 256>>>(yln, wq, nullptr, q, BT, D_MODEL, D_MODEL, 0, 0, 0, 0);
        sgemm_nn<<<grid_proj, 256>>>(yln, wk, nullptr, k, BT, D_MODEL, D_MODEL, 0, 0, 0, 0);
        sgemm_nn<<<grid_proj, 256>>>(yln, wv, nullptr, v, BT, D_MODEL, D_MODEL, 0, 0, 0, 0);

        // S = (Q K^T) / sqrt(D)
        sgemm_nt<<<grid_attn, 256>>>(q, k, s, SEQ, SEQ, D_MODEL, SD, SD, SS, 0.03125f);

        softmax_kernel<<<NB * SEQ, 256>>>(s);

        // O = S V
        sgemm_nn<<<grid_attn, 256>>>(s, v, nullptr, o, SEQ, D_MODEL, SEQ, SS, SD, SD, 0);

        ln_kernel<<<BT, 256>>>(o, g2, b2, yln);

        // H = relu(Y W1 + b1)
        sgemm_nn<<<grid_proj, 256>>>(yln, w1, bb1, h, BT, D_MODEL, D_MODEL, 0, 0, 0, 4 | 1);
        // Z += H W2 + b2
        sgemm_nn<<<grid_proj, 256>>>(h, w2, bb2, z, BT, D_MODEL, D_MODEL, 0, 0, 0, 4 | 2);
    }

    // logits = Z enc^T   (M=4096, N=32000, K=1024)
    dim3 grid_logits(D_VOCAB / 128, BT / 128);    // (250, 32)
    sgemm_nt<<<grid_logits, 256>>>(z, enc, out, BT, D_VOCAB, D_MODEL, 0, 0, 0, 1.0f);

    // loss = mean(logsumexp - logit_y)
    nll_kernel<<<BT, 256>>>(out, y, nll);
    if ((long)out_size > BTV)
        loss_reduce_kernel<<<1, 256>>>(nll, out, BTV);
}

// round 4
// speedup vs baseline: 2.4159x; 2.4159x over previous
#include <cuda_runtime.h>
#include <cuda_bf16.h>
#include <cstdint>
#include <math.h>

#define D_MODEL 1024
#define D_VOCAB 32000
#define NB 4
#define SEQ 1024
#define BT (NB * SEQ)
#define NLAYERS 6
#define BTV ((long)BT * D_VOCAB)

// ---------------- scratch (device globals) ----------------------------------
__device__ float g_z  [BT * D_MODEL];
__device__ float g_yln[BT * D_MODEL];
__device__ float g_q  [BT * D_MODEL];
__device__ float g_k  [BT * D_MODEL];
__device__ float g_v  [BT * D_MODEL];
__device__ float g_vT [BT * D_MODEL];
__device__ float g_s  [NB * SEQ * SEQ];
__device__ float g_o  [BT * D_MODEL];
__device__ float g_h  [BT * D_MODEL];
__device__ float g_wt [5 * D_MODEL * D_MODEL];   // wqT, wkT, wvT, w1T, w2T
__device__ float g_nll[BT];

// ---------------- helpers ----------------------------------------------------
__device__ __forceinline__ uint32_t smem_u32(const void* p) {
    uint32_t a;
    asm("{ .reg .u64 t; cvta.to.shared.u64 t, %1; cvt.u32.u64 %0, t; }" : "=r"(a) : "l"(p));
    return a;
}

// split fp32 pair -> packed hi bf16x2 + lo bf16x2
__device__ __forceinline__ void split2(float x0, float x1, uint32_t& hp, uint32_t& lp) {
    __nv_bfloat16 h0 = __float2bfloat16(x0);
    __nv_bfloat16 h1 = __float2bfloat16(x1);
    float r0 = x0 - __bfloat162float(h0);
    float r1 = x1 - __bfloat162float(h1);
    __nv_bfloat16 l0 = __float2bfloat16(r0);
    __nv_bfloat16 l1 = __float2bfloat16(r1);
    hp = (uint32_t)__bfloat16_as_ushort(h0) | ((uint32_t)__bfloat16_as_ushort(h1) << 16);
    lp = (uint32_t)__bfloat16_as_ushort(l0) | ((uint32_t)__bfloat16_as_ushort(l1) << 16);
}

__device__ __forceinline__ void ldsm4(uint32_t addr, uint32_t& r0, uint32_t& r1,
                                      uint32_t& r2, uint32_t& r3) {
    asm volatile("ldmatrix.sync.aligned.m8n8.x4.shared.b16 {%0,%1,%2,%3}, [%4];"
                 : "=r"(r0), "=r"(r1), "=r"(r2), "=r"(r3) : "r"(addr));
}

__device__ __forceinline__ void mma_bf16(float* c, uint32_t a0, uint32_t a1,
                                         uint32_t a2, uint32_t a3,
                                         uint32_t b0, uint32_t b1) {
    asm volatile(
        "mma.sync.aligned.m16n8k16.row.col.f32.bf16.bf16.f32 "
        "{%0,%1,%2,%3}, {%4,%5,%6,%7}, {%8,%9}, {%0,%1,%2,%3};"
        : "+f"(c[0]), "+f"(c[1]), "+f"(c[2]), "+f"(c[3])
        : "r"(a0), "r"(a1), "r"(a2), "r"(a3), "r"(b0), "r"(b1));
}

// ---------------- mma.sync GEMM NT: C = alpha * A(MxK) * B(NxK)^T ------------
// flags: 1=relu, 2=accumulate into C, 4=add bias
// grid: (M/128, N/128, batch), 256 threads. K % 32 == 0, M,N % 128 == 0.
__global__ __launch_bounds__(256, 2) void gemm_nt_mma(
    const float* __restrict__ A, const float* __restrict__ B,
    const float* __restrict__ bias, float* __restrict__ C,
    int M, int N, int K, long sA, long sB, long sC, float alpha, int flags) {

    __shared__ __align__(16) uint8_t sm[4 * 8192];   // Ah, Al, Bh, Bl : 128 x 64B
    uint8_t* sAh = sm;
    uint8_t* sAl = sm + 8192;
    uint8_t* sBh = sm + 16384;
    uint8_t* sBl = sm + 24576;

    A += (long)blockIdx.z * sA;
    B += (long)blockIdx.z * sB;
    C += (long)blockIdx.z * sC;

    const int tid  = threadIdx.x;
    const int wid  = tid >> 5;
    const int lane = tid & 31;
    const int warp_m = wid & 3;        // 0..3 -> m tile 32
    const int warp_n = wid >> 2;       // 0..1 -> n tile 64
    const int row0 = blockIdx.x * 128;
    const int col0 = blockIdx.y * 128;

    const uint32_t aBaseH = smem_u32(sAh);
    const uint32_t aBaseL = smem_u32(sAl);
    const uint32_t bBaseH = smem_u32(sBh);
    const uint32_t bBaseL = smem_u32(sBl);

    // loader mapping: each thread owns one half-row (16 floats) of A and of B
    const int lr = tid >> 1;           // 0..127
    const int lq = tid & 1;            // 0/1 half
    const float* Ap = A + (long)(row0 + lr) * K + lq * 16;
    const float* Bp = B + (long)(col0 + lr) * K + lq * 16;

    float acc[2][8][4];
    #pragma unroll
    for (int mb = 0; mb < 2; mb++)
        #pragma unroll
        for (int nb = 0; nb < 8; nb++)
            #pragma unroll
            for (int i = 0; i < 4; i++) acc[mb][nb][i] = 0.f;

    const int swz = (lr >> 1) & 3;

    for (int k0 = 0; k0 < K; k0 += 32) {
        // ---- load + split-convert into swizzled smem ----
        #pragma unroll
        for (int j = 0; j < 2; j++) {
            int c  = lq * 2 + j;
            int pc = c ^ swz;
            uint32_t off = (uint32_t)(lr * 64 + pc * 16);

            float4 f0 = *(const float4*)(Ap + k0 + j * 8);
            float4 f1 = *(const float4*)(Ap + k0 + j * 8 + 4);
            uint4 h, l;
            split2(f0.x, f0.y, h.x, l.x); split2(f0.z, f0.w, h.y, l.y);
            split2(f1.x, f1.y, h.z, l.z); split2(f1.z, f1.w, h.w, l.w);
            *(uint4*)(sAh + off) = h;
            *(uint4*)(sAl + off) = l;

            f0 = *(const float4*)(Bp + k0 + j * 8);
            f1 = *(const float4*)(Bp + k0 + j * 8 + 4);
            split2(f0.x, f0.y, h.x, l.x); split2(f0.z, f0.w, h.y, l.y);
            split2(f1.x, f1.y, h.z, l.z); split2(f1.z, f1.w, h.w, l.w);
            *(uint4*)(sBh + off) = h;
            *(uint4*)(sBl + off) = l;
        }
        __syncthreads();

        // ---- two k16 sub-steps ----
        #pragma unroll
        for (int kc = 0; kc < 2; kc++) {
            // B fragments: 8 n-blocks (hi+lo)
            uint32_t bh[8][2], bl[8][2];
            #pragma unroll
            for (int nb4 = 0; nb4 < 4; nb4++) {
                int nrow  = warp_n * 64 + nb4 * 16 + (lane & 15);
                int chunk = kc * 2 + (lane >> 4);
                uint32_t off = (uint32_t)(nrow * 64 + (chunk ^ ((nrow >> 1) & 3)) * 16);
                uint32_t r0, r1, r2, r3;
                ldsm4(bBaseH + off, r0, r1, r2, r3);
                bh[nb4 * 2][0] = r0; bh[nb4 * 2 + 1][0] = r1;
                bh[nb4 * 2][1] = r2; bh[nb4 * 2 + 1][1] = r3;
                ldsm4(bBaseL + off, r0, r1, r2, r3);
                bl[nb4 * 2][0] = r0; bl[nb4 * 2 + 1][0] = r1;
                bl[nb4 * 2][1] = r2; bl[nb4 * 2 + 1][1] = r3;
            }
            #pragma unroll
            for (int mb = 0; mb < 2; mb++) {
                int mrow  = warp_m * 32 + mb * 16 + (lane & 15);
                int chunk = kc * 2 + (lane >> 4);
                uint32_t off = (uint32_t)(mrow * 64 + (chunk ^ ((mrow >> 1) & 3)) * 16);
                uint32_t ah0, ah1, ah2, ah3, al0, al1, al2, al3;
                ldsm4(aBaseH + off, ah0, ah1, ah2, ah3);
                ldsm4(aBaseL + off, al0, al1, al2, al3);
                #pragma unroll
                for (int nb = 0; nb < 8; nb++) {
                    mma_bf16(acc[mb][nb], ah0, ah1, ah2, ah3, bh[nb][0], bh[nb][1]);
                    mma_bf16(acc[mb][nb], ah0, ah1, ah2, ah3, bl[nb][0], bl[nb][1]);
                    mma_bf16(acc[mb][nb], al0, al1, al2, al3, bh[nb][0], bh[nb][1]);
                }
            }
        }
        __syncthreads();
    }

    // ---- epilogue ----
    #pragma unroll
    for (int mb = 0; mb < 2; mb++) {
        #pragma unroll
        for (int nb = 0; nb < 8; nb++) {
            int m0 = row0 + warp_m * 32 + mb * 16 + (lane >> 2);
            int n0 = col0 + warp_n * 64 + nb * 8 + (lane & 3) * 2;
            #pragma unroll
            for (int half = 0; half < 2; half++) {
                int m = m0 + half * 8;
                float v0 = acc[mb][nb][half * 2 + 0] * alpha;
                float v1 = acc[mb][nb][half * 2 + 1] * alpha;
                if (flags & 4) { v0 += bias[n0]; v1 += bias[n0 + 1]; }
                if (flags & 1) { v0 = fmaxf(v0, 0.f); v1 = fmaxf(v1, 0.f); }
                float2* cp = (float2*)(C + (long)m * N + n0);
                if (flags & 2) { float2 o = *cp; v0 += o.x; v1 += o.y; }
                *cp = make_float2(v0, v1);
            }
        }
    }
}

// ---------------- transpose: dst(C x R) = src(R x C)^T, batched via z --------
__global__ void transpose_kernel(const float* __restrict__ src, float* __restrict__ dst,
                                 int R, int Ccols) {
    __shared__ float t[32][33];
    long ofs = (long)blockIdx.z * R * Ccols;
    src += ofs; dst += ofs;
    int bx = blockIdx.x * 32, by = blockIdx.y * 32;
    int x = bx + threadIdx.x;
    #pragma unroll
    for (int j = 0; j < 32; j += 8) {
        int y = by + threadIdx.y + j;
        t[threadIdx.y + j][threadIdx.x] = src[(long)y * Ccols + x];
    }
    __syncthreads();
    x = by + threadIdx.x;
    #pragma unroll
    for (int j = 0; j < 32; j += 8) {
        int y = bx + threadIdx.y + j;
        dst[(long)y * R + x] = t[threadIdx.x][threadIdx.y + j];
    }
}

// ---------------- embedding gather ------------------------------------------
__global__ void embed_kernel(const int* __restrict__ x, const float* __restrict__ enc,
                             float* __restrict__ z) {
    int row = blockIdx.x;
    int tok = x[row];
    const float4* src = (const float4*)(enc + (long)tok * D_MODEL);
    float4* dst = (float4*)(z + (long)row * D_MODEL);
    for (int i = threadIdx.x; i < D_MODEL / 4; i += blockDim.x) dst[i] = src[i];
}

// ---------------- (buggy) LayerNorm -----------------------------------------
__global__ void ln_kernel(const float* __restrict__ in, const float* __restrict__ gamma,
                          const float* __restrict__ beta, float* __restrict__ out) {
    int row = blockIdx.x;
    const float* xr = in + (long)row * D_MODEL;
    __shared__ float red[256];
    int tid = threadIdx.x;

    float s = 0.f;
    for (int i = tid; i < D_MODEL; i += 256) s += xr[i];
    red[tid] = s; __syncthreads();
    #pragma unroll
    for (int o = 128; o > 0; o >>= 1) { if (tid < o) red[tid] += red[tid + o]; __syncthreads(); }
    float mu = red[0] / (float)D_MODEL;
    __syncthreads();

    float s2 = 0.f;
    for (int i = tid; i < D_MODEL; i += 256) { float d = xr[i] - mu; s2 += d * d; }
    red[tid] = s2; __syncthreads();
    #pragma unroll
    for (int o = 128; o > 0; o >>= 1) { if (tid < o) red[tid] += red[tid + o]; __syncthreads(); }
    float var = red[0] / (float)(D_MODEL - 1);
    float shift = mu * rsqrtf(var);

    float* orow = out + (long)row * D_MODEL;
    for (int i = tid; i < D_MODEL; i += 256)
        orow[i] = (xr[i] - shift) * gamma[i] + beta[i];
}

// ---------------- row softmax over SEQ --------------------------------------
__global__ void softmax_kernel(float* __restrict__ s) {
    int row = blockIdx.x;
    float* r = s + (long)row * SEQ;
    __shared__ float red[256];
    int tid = threadIdx.x;

    float m = -1e30f;
    for (int i = tid; i < SEQ; i += 256) m = fmaxf(m, r[i]);
    red[tid] = m; __syncthreads();
    #pragma unroll
    for (int o = 128; o > 0; o >>= 1) { if (tid < o) red[tid] = fmaxf(red[tid], red[tid + o]); __syncthreads(); }
    float mx = red[0]; __syncthreads();

    float sum = 0.f;
    for (int i = tid; i < SEQ; i += 256) { float e = expf(r[i] - mx); r[i] = e; sum += e; }
    red[tid] = sum; __syncthreads();
    #pragma unroll
    for (int o = 128; o > 0; o >>= 1) { if (tid < o) red[tid] += red[tid + o]; __syncthreads(); }
    float inv = 1.f / red[0];
    for (int i = tid; i < SEQ; i += 256) r[i] *= inv;
}

// ---------------- per-row NLL over V=32000 ----------------------------------
__global__ void nll_kernel(const float* __restrict__ logits, const int* __restrict__ y,
                           float* __restrict__ nll) {
    int row = blockIdx.x;
    const float* r = logits + (long)row * D_VOCAB;
    __shared__ float red[256];
    int tid = threadIdx.x;

    float m = -1e30f;
    for (int i = tid; i < D_VOCAB; i += 256) m = fmaxf(m, r[i]);
    red[tid] = m; __syncthreads();
    #pragma unroll
    for (int o = 128; o > 0; o >>= 1) { if (tid < o) red[tid] = fmaxf(red[tid], red[tid + o]); __syncthreads(); }
    float mx = red[0]; __syncthreads();

    float s = 0.f;
    for (int i = tid; i < D_VOCAB; i += 256) s += expf(r[i] - mx);
    red[tid] = s; __syncthreads();
    #pragma unroll
    for (int o = 128; o > 0; o >>= 1) { if (tid < o) red[tid] += red[tid + o]; __syncthreads(); }

    if (tid == 0) nll[row] = (mx + logf(red[0])) - r[y[row]];
}

__global__ void loss_reduce_kernel(const float* __restrict__ nll, float* __restrict__ out,
                                   long ofs) {
    __shared__ float red[256];
    int tid = threadIdx.x;
    float s = 0.f;
    for (int i = tid; i < BT; i += 256) s += nll[i];
    red[tid] = s; __syncthreads();
    #pragma unroll
    for (int o = 128; o > 0; o >>= 1) { if (tid < o) red[tid] += red[tid + o]; __syncthreads(); }
    if (tid == 0) out[ofs] = red[0] / (float)BT;
}

// ---------------- driver -----------------------------------------------------
extern "C" void kernel_launch(void* const* d_in, const int* in_sizes, int n_in,
                              void* d_out, int out_size) {
    (void)in_sizes; (void)n_in;
    const int*   x   = (const int*)  d_in[0];
    const int*   y   = (const int*)  d_in[1];
    const float* enc = (const float*)d_in[2];
    const float* g1  = (const float*)d_in[3];
    const float* b1  = (const float*)d_in[4];
    const float* wq  = (const float*)d_in[5];
    const float* wk  = (const float*)d_in[6];
    const float* wv  = (const float*)d_in[7];
    const float* g2  = (const float*)d_in[8];
    const float* b2  = (const float*)d_in[9];
    const float* w1  = (const float*)d_in[10];
    const float* bb1 = (const float*)d_in[11];
    const float* w2  = (const float*)d_in[12];
    const float* bb2 = (const float*)d_in[13];
    float* out = (float*)d_out;

    float *z, *yln, *q, *k, *v, *vT, *s, *o, *h, *wt, *nll;
    cudaGetSymbolAddress((void**)&z,   g_z);
    cudaGetSymbolAddress((void**)&yln, g_yln);
    cudaGetSymbolAddress((void**)&q,   g_q);
    cudaGetSymbolAddress((void**)&k,   g_k);
    cudaGetSymbolAddress((void**)&v,   g_v);
    cudaGetSymbolAddress((void**)&vT,  g_vT);
    cudaGetSymbolAddress((void**)&s,   g_s);
    cudaGetSymbolAddress((void**)&o,   g_o);
    cudaGetSymbolAddress((void**)&h,   g_h);
    cudaGetSymbolAddress((void**)&wt,  g_wt);
    cudaGetSymbolAddress((void**)&nll, g_nll);

    const long DD = (long)D_MODEL * D_MODEL;
    const long SD = (long)SEQ * D_MODEL;
    const long SS = (long)SEQ * SEQ;
    float* wqT = wt + 0 * DD;
    float* wkT = wt + 1 * DD;
    float* wvT = wt + 2 * DD;
    float* w1T = wt + 3 * DD;
    float* w2T = wt + 4 * DD;

    dim3 tgrid(D_MODEL / 32, D_MODEL / 32, 1);
    dim3 tblk(32, 8);
    transpose_kernel<<<tgrid, tblk>>>(wq, wqT, D_MODEL, D_MODEL);
    transpose_kernel<<<tgrid, tblk>>>(wk, wkT, D_MODEL, D_MODEL);
    transpose_kernel<<<tgrid, tblk>>>(wv, wvT, D_MODEL, D_MODEL);
    transpose_kernel<<<tgrid, tblk>>>(w1, w1T, D_MODEL, D_MODEL);
    transpose_kernel<<<tgrid, tblk>>>(w2, w2T, D_MODEL, D_MODEL);

    embed_kernel<<<BT, 256>>>(x, enc, z);

    dim3 grid_proj(BT / 128, D_MODEL / 128);       // (32, 8)
    dim3 grid_attn(SEQ / 128, SEQ / 128, NB);      // (8, 8, 4)
    dim3 tgrid_v(D_MODEL / 32, SEQ / 32, NB);

    for (int layer = 0; layer < NLAYERS; layer++) {
        ln_kernel<<<BT, 256>>>(z, g1, b1, yln);

        gemm_nt_mma<<<grid_proj, 256>>>(yln, wqT, nullptr, q, BT, D_MODEL, D_MODEL, 0, 0, 0, 1.f, 0);
        gemm_nt_mma<<<grid_proj, 256>>>(yln, wkT, nullptr, k, BT, D_MODEL, D_MODEL, 0, 0, 0, 1.f, 0);
        gemm_nt_mma<<<grid_proj, 256>>>(yln, wvT, nullptr, v, BT, D_MODEL, D_MODEL, 0, 0, 0, 1.f, 0);

        // S = (Q K^T) / 32
        gemm_nt_mma<<<grid_attn, 256>>>(q, k, nullptr, s, SEQ, SEQ, D_MODEL, SD, SD, SS, 0.03125f, 0);

        softmax_kernel<<<NB * SEQ, 256>>>(s);

        // vT_b = V_b^T  (per batch: SEQ x D -> D x SEQ)
        transpose_kernel<<<tgrid_v, tblk>>>(v, vT, SEQ, D_MODEL);
        // O = S V  -> NT with B = V^T
        gemm_nt_mma<<<grid_attn, 256>>>(s, vT, nullptr, o, SEQ, D_MODEL, SEQ, SS, SD, SD, 1.f, 0);

        ln_kernel<<<BT, 256>>>(o, g2, b2, yln);

        // H = relu(Y W1 + b1)
        gemm_nt_mma<<<grid_proj, 256>>>(yln, w1T, bb1, h, BT, D_MODEL, D_MODEL, 0, 0, 0, 1.f, 4 | 1);
        // Z += H W2 + b2
        gemm_nt_mma<<<grid_proj, 256>>>(h, w2T, bb2, z, BT, D_MODEL, D_MODEL, 0, 0, 0, 1.f, 4 | 2);
    }

    // logits = Z enc^T   (M=4096, N=32000, K=1024) — enc is already (V, D)
    dim3 grid_logits(BT / 128, D_VOCAB / 128);     // (32, 250)
    gemm_nt_mma<<<grid_logits, 256>>>(z, enc, nullptr, out, BT, D_VOCAB, D_MODEL, 0, 0, 0, 1.f, 0);

    nll_kernel<<<BT, 256>>>(out, y, nll);
    if ((long)out_size > BTV)
        loss_reduce_kernel<<<1, 256>>>(nll, out, BTV);
}